// round 1
// baseline (speedup 1.0000x reference)
#include <cuda_runtime.h>

#define HIDDEN 2048
#define NHEADS 32
#define NKV 8
#define HEAD 64
#define BATCH 2
#define SEQ 2048
#define MTOT (BATCH * SEQ)      // 4096
#define KVDIM (NKV * HEAD)      // 512

// Scratch (allocation-free rule: __device__ globals)
__device__ float g_Q[MTOT * HIDDEN];     // [b,s, h*64+d]
__device__ float g_K[MTOT * KVDIM];      // [b,s, kvh*64+d]
__device__ float g_V[MTOT * KVDIM];
__device__ float g_attn[MTOT * HIDDEN];  // [b,s, h*64+d]

__device__ __forceinline__ float ex2f(float x) {
    float y;
    asm("ex2.approx.ftz.f32 %0, %1;" : "=f"(y) : "f"(x));
    return y;
}

// ---------------------------------------------------------------------------
// C[M,N] = A[M,K] * B[N,K]^T (+bias).  A,B row-major (both K-major -> NT gemm)
// BM=BN=128, BK=16, 256 threads, 8x8 per thread.
// ---------------------------------------------------------------------------
__device__ __forceinline__ void gemm_nt_body(
    const float* __restrict__ A, const float* __restrict__ Bw,
    float* __restrict__ C, int M, int N, int K,
    const float* __restrict__ bias)
{
    constexpr int BM = 128, BN = 128, BK = 16;
    __shared__ __align__(16) float As[BK][BM + 4];
    __shared__ __align__(16) float Bs[BK][BN + 4];

    const int tid = threadIdx.x;
    const int tx = tid & 15;       // N dim
    const int ty = tid >> 4;       // M dim
    const int m0 = blockIdx.y * BM;
    const int n0 = blockIdx.x * BN;
    const int lrow = tid >> 2;            // 0..63
    const int lcol = (tid & 3) << 2;      // 0,4,8,12

    const float* Ap = A + (size_t)(m0 + lrow) * K + lcol;
    const float* Bp = Bw + (size_t)(n0 + lrow) * K + lcol;

    float acc[8][8];
#pragma unroll
    for (int i = 0; i < 8; i++)
#pragma unroll
        for (int j = 0; j < 8; j++) acc[i][j] = 0.f;

    for (int k0 = 0; k0 < K; k0 += BK) {
#pragma unroll
        for (int i = 0; i < 2; i++) {
            float4 a = *(const float4*)(Ap + (size_t)i * 64 * K + k0);
            As[lcol + 0][lrow + i * 64] = a.x;
            As[lcol + 1][lrow + i * 64] = a.y;
            As[lcol + 2][lrow + i * 64] = a.z;
            As[lcol + 3][lrow + i * 64] = a.w;
            float4 b = *(const float4*)(Bp + (size_t)i * 64 * K + k0);
            Bs[lcol + 0][lrow + i * 64] = b.x;
            Bs[lcol + 1][lrow + i * 64] = b.y;
            Bs[lcol + 2][lrow + i * 64] = b.z;
            Bs[lcol + 3][lrow + i * 64] = b.w;
        }
        __syncthreads();
#pragma unroll
        for (int kk = 0; kk < BK; kk++) {
            float4 a0 = *(const float4*)&As[kk][ty * 8];
            float4 a1 = *(const float4*)&As[kk][ty * 8 + 4];
            float4 b0 = *(const float4*)&Bs[kk][tx * 8];
            float4 b1 = *(const float4*)&Bs[kk][tx * 8 + 4];
            float ar[8] = {a0.x, a0.y, a0.z, a0.w, a1.x, a1.y, a1.z, a1.w};
            float br[8] = {b0.x, b0.y, b0.z, b0.w, b1.x, b1.y, b1.z, b1.w};
#pragma unroll
            for (int i = 0; i < 8; i++)
#pragma unroll
                for (int j = 0; j < 8; j++)
                    acc[i][j] = fmaf(ar[i], br[j], acc[i][j]);
        }
        __syncthreads();
    }

    float breg[8];
#pragma unroll
    for (int j = 0; j < 8; j++)
        breg[j] = bias ? bias[n0 + tx * 8 + j] : 0.f;

#pragma unroll
    for (int i = 0; i < 8; i++) {
        float* Cp = C + (size_t)(m0 + ty * 8 + i) * N + n0 + tx * 8;
        float4 c0 = make_float4(acc[i][0] + breg[0], acc[i][1] + breg[1],
                                acc[i][2] + breg[2], acc[i][3] + breg[3]);
        float4 c1 = make_float4(acc[i][4] + breg[4], acc[i][5] + breg[5],
                                acc[i][6] + breg[6], acc[i][7] + breg[7]);
        *(float4*)(Cp) = c0;
        *(float4*)(Cp + 4) = c1;
    }
}

__global__ __launch_bounds__(256, 2)
void gemm_nt(const float* __restrict__ A, const float* __restrict__ Bw,
             float* __restrict__ C, int M, int N, int K,
             const float* __restrict__ bias)
{
    gemm_nt_body(A, Bw, C, M, N, K, bias);
}

// K and V projections fused into one launch via blockIdx.z (keeps grid large
// enough to fill 148 SMs despite N=512).
__global__ __launch_bounds__(256, 2)
void gemm_nt_kv(const float* __restrict__ A,
                const float* __restrict__ Wk, const float* __restrict__ Wv,
                float* __restrict__ Ck, float* __restrict__ Cv,
                int M, int N, int K)
{
    if (blockIdx.z == 0)
        gemm_nt_body(A, Wk, Ck, M, N, K, nullptr);
    else
        gemm_nt_body(A, Wv, Cv, M, N, K, nullptr);
}

// ---------------------------------------------------------------------------
// Flash attention, fp32. Br=Bc=64, D=64, 256 threads (16x16), 4x4 per thread.
// smem: Qst [d][row] (scale*log2e folded in), Kst [d][col] XOR-swizzled,
//       Vs [kv][d], Ps [row][kv].  64 KB dynamic -> 2 CTAs/SM.
// ---------------------------------------------------------------------------
__global__ __launch_bounds__(256, 2)
void flash_attn_kernel()
{
    extern __shared__ __align__(16) float sm[];
    float* Qst = sm;                 // 64*64, index d*64 + row
    float* Kst = sm + 64 * 64;       // 64*64, index d*64 + (col ^ (d & 60))
    float* Vs  = sm + 2 * 64 * 64;   // 64*64, index kv*64 + d
    float* Ps  = sm + 3 * 64 * 64;   // 64*64, index row*64 + kv

    const int tid = threadIdx.x;
    const int tx = tid & 15;   // cols (kv for S, d for O)
    const int ty = tid >> 4;   // rows (q)
    const int q0 = blockIdx.x * 64;
    const int h  = blockIdx.y;
    const int b  = blockIdx.z;
    const int kvh = h >> 2;    // GQA: 4 q-heads per kv-head, contiguous

    const float* Qg = g_Q + (size_t)(b * SEQ + q0) * HIDDEN + h * HEAD;
    const float* Kg = g_K + (size_t)(b * SEQ) * KVDIM + kvh * HEAD;
    const float* Vg = g_V + (size_t)(b * SEQ) * KVDIM + kvh * HEAD;

    const float sc = 0.125f * 1.4426950408889634f;  // head^-0.5 * log2(e)

    // Load Q tile transposed (scale folded in). One-time cost; plain layout.
#pragma unroll
    for (int i = 0; i < 4; i++) {
        int id = tid + i * 256;
        int row = id >> 4;
        int d = (id & 15) << 2;
        float4 q = *(const float4*)(Qg + (size_t)row * HIDDEN + d);
        Qst[(d + 0) * 64 + row] = q.x * sc;
        Qst[(d + 1) * 64 + row] = q.y * sc;
        Qst[(d + 2) * 64 + row] = q.z * sc;
        Qst[(d + 3) * 64 + row] = q.w * sc;
    }

    float mrow[4], lacc[4], o[4][4];
#pragma unroll
    for (int r = 0; r < 4; r++) {
        mrow[r] = -1e30f;
        lacc[r] = 0.f;
#pragma unroll
        for (int j = 0; j < 4; j++) o[r][j] = 0.f;
    }

    for (int kv0 = 0; kv0 < SEQ; kv0 += 64) {
        __syncthreads();  // prior tile's consumers done; Q visible on iter 0
#pragma unroll
        for (int i = 0; i < 4; i++) {
            int id = tid + i * 256;
            int row = id >> 4;
            int d = (id & 15) << 2;
            float4 k4 = *(const float4*)(Kg + (size_t)(kv0 + row) * KVDIM + d);
            // element (d+j, row) -> (d+j)*64 + (row ^ ((d+j)&60)); (d+j)&60 == d&60
            int swr = row ^ (d & 60);
            Kst[(d + 0) * 64 + swr] = k4.x;
            Kst[(d + 1) * 64 + swr] = k4.y;
            Kst[(d + 2) * 64 + swr] = k4.z;
            Kst[(d + 3) * 64 + swr] = k4.w;
            float4 v4 = *(const float4*)(Vg + (size_t)(kv0 + row) * KVDIM + d);
            *(float4*)&Vs[row * 64 + d] = v4;
        }
        __syncthreads();

        // S = (Q*sc) K^T  (already includes log2e)
        float s[4][4];
#pragma unroll
        for (int r = 0; r < 4; r++)
#pragma unroll
            for (int c = 0; c < 4; c++) s[r][c] = 0.f;

#pragma unroll 16
        for (int d = 0; d < 64; d++) {
            float4 q = *(const float4*)&Qst[d * 64 + ty * 4];
            float4 k = *(const float4*)&Kst[d * 64 + ((tx * 4) ^ (d & 60))];
            s[0][0] = fmaf(q.x, k.x, s[0][0]);
            s[0][1] = fmaf(q.x, k.y, s[0][1]);
            s[0][2] = fmaf(q.x, k.z, s[0][2]);
            s[0][3] = fmaf(q.x, k.w, s[0][3]);
            s[1][0] = fmaf(q.y, k.x, s[1][0]);
            s[1][1] = fmaf(q.y, k.y, s[1][1]);
            s[1][2] = fmaf(q.y, k.z, s[1][2]);
            s[1][3] = fmaf(q.y, k.w, s[1][3]);
            s[2][0] = fmaf(q.z, k.x, s[2][0]);
            s[2][1] = fmaf(q.z, k.y, s[2][1]);
            s[2][2] = fmaf(q.z, k.z, s[2][2]);
            s[2][3] = fmaf(q.z, k.w, s[2][3]);
            s[3][0] = fmaf(q.w, k.x, s[3][0]);
            s[3][1] = fmaf(q.w, k.y, s[3][1]);
            s[3][2] = fmaf(q.w, k.z, s[3][2]);
            s[3][3] = fmaf(q.w, k.w, s[3][3]);
        }

        // Online softmax (base-2); row reduction over the 16 tx lanes.
#pragma unroll
        for (int r = 0; r < 4; r++) {
            float mx = fmaxf(fmaxf(s[r][0], s[r][1]), fmaxf(s[r][2], s[r][3]));
#pragma unroll
            for (int off = 8; off >= 1; off >>= 1)
                mx = fmaxf(mx, __shfl_xor_sync(0xffffffffu, mx, off));
            float mnew = fmaxf(mrow[r], mx);
            float alpha = ex2f(mrow[r] - mnew);
            mrow[r] = mnew;
            float p0 = ex2f(s[r][0] - mnew);
            float p1 = ex2f(s[r][1] - mnew);
            float p2 = ex2f(s[r][2] - mnew);
            float p3 = ex2f(s[r][3] - mnew);
            float rs = (p0 + p1) + (p2 + p3);
#pragma unroll
            for (int off = 8; off >= 1; off >>= 1)
                rs += __shfl_xor_sync(0xffffffffu, rs, off);
            lacc[r] = lacc[r] * alpha + rs;
            o[r][0] *= alpha;
            o[r][1] *= alpha;
            o[r][2] *= alpha;
            o[r][3] *= alpha;
            *(float4*)&Ps[(ty * 4 + r) * 64 + tx * 4] = make_float4(p0, p1, p2, p3);
        }
        __syncthreads();

        // O += P V
#pragma unroll 16
        for (int kv = 0; kv < 64; kv++) {
            float4 v = *(const float4*)&Vs[kv * 64 + tx * 4];
            float pa = Ps[(ty * 4 + 0) * 64 + kv];
            float pb = Ps[(ty * 4 + 1) * 64 + kv];
            float pc = Ps[(ty * 4 + 2) * 64 + kv];
            float pd = Ps[(ty * 4 + 3) * 64 + kv];
            o[0][0] = fmaf(pa, v.x, o[0][0]);
            o[0][1] = fmaf(pa, v.y, o[0][1]);
            o[0][2] = fmaf(pa, v.z, o[0][2]);
            o[0][3] = fmaf(pa, v.w, o[0][3]);
            o[1][0] = fmaf(pb, v.x, o[1][0]);
            o[1][1] = fmaf(pb, v.y, o[1][1]);
            o[1][2] = fmaf(pb, v.z, o[1][2]);
            o[1][3] = fmaf(pb, v.w, o[1][3]);
            o[2][0] = fmaf(pc, v.x, o[2][0]);
            o[2][1] = fmaf(pc, v.y, o[2][1]);
            o[2][2] = fmaf(pc, v.z, o[2][2]);
            o[2][3] = fmaf(pc, v.w, o[2][3]);
            o[3][0] = fmaf(pd, v.x, o[3][0]);
            o[3][1] = fmaf(pd, v.y, o[3][1]);
            o[3][2] = fmaf(pd, v.z, o[3][2]);
            o[3][3] = fmaf(pd, v.w, o[3][3]);
        }
    }

    float* Og = g_attn + (size_t)(b * SEQ + q0) * HIDDEN + h * HEAD;
#pragma unroll
    for (int r = 0; r < 4; r++) {
        float inv = 1.f / lacc[r];
        float4 ov = make_float4(o[r][0] * inv, o[r][1] * inv,
                                o[r][2] * inv, o[r][3] * inv);
        *(float4*)(Og + (size_t)(ty * 4 + r) * HIDDEN + tx * 4) = ov;
    }
}

// ---------------------------------------------------------------------------

extern "C" void kernel_launch(void* const* d_in, const int* in_sizes, int n_in,
                              void* d_out, int out_size)
{
    const float* x  = (const float*)d_in[0];
    const float* Wq = (const float*)d_in[1];
    const float* Wk = (const float*)d_in[2];
    const float* Wv = (const float*)d_in[3];
    const float* Wo = (const float*)d_in[4];
    const float* bo = (const float*)d_in[5];
    float* out = (float*)d_out;

    float *Qp, *Kp, *Vp, *Ap;
    cudaGetSymbolAddress((void**)&Qp, g_Q);
    cudaGetSymbolAddress((void**)&Kp, g_K);
    cudaGetSymbolAddress((void**)&Vp, g_V);
    cudaGetSymbolAddress((void**)&Ap, g_attn);

    const int smem_flash = 4 * 64 * 64 * (int)sizeof(float);  // 64 KB
    cudaFuncSetAttribute(flash_attn_kernel,
                         cudaFuncAttributeMaxDynamicSharedMemorySize, smem_flash);

    // Q projection: [4096,2048] = x[4096,2048] @ Wq[2048,2048]^T
    gemm_nt<<<dim3(HIDDEN / 128, MTOT / 128), 256>>>(x, Wq, Qp, MTOT, HIDDEN, HIDDEN, nullptr);
    // K and V projections fused (N=512 each)
    gemm_nt_kv<<<dim3(KVDIM / 128, MTOT / 128, 2), 256>>>(x, Wk, Wv, Kp, Vp, MTOT, KVDIM, HIDDEN);
    // Attention
    flash_attn_kernel<<<dim3(SEQ / 64, NHEADS, BATCH), 256, smem_flash>>>();
    // Output projection + bias
    gemm_nt<<<dim3(HIDDEN / 128, MTOT / 128), 256>>>(Ap, Wo, out, MTOT, HIDDEN, HIDDEN, bo);
}